// round 5
// baseline (speedup 1.0000x reference)
#include <cuda_runtime.h>
#include <cstdint>

#define T_LEN   1000000
#define HIDDEN  75
#define NS      16
#define BS      64                 // steps per checkpoint block
#define NBLK    (T_LEN / BS)       // 15625
#define RB      8                  // ring blocks (smem)

// Scratch: negated log-priors in EVEN/ODD-permuted layout per step:
//   arr[0..7]  = np_{0,2,4,...,14}  (E half)
//   arr[8..15] = np_{1,3,5,...,15}  (O half)
// and 8-state checkpoints in packed layout [p0,p2,p4,p6, p1,p3,p5,p7].
__device__ float g_np[T_LEN * 16];     // 64 MB
__device__ float g_ckpt[NBLK * 8];     // 500 KB

__device__ __forceinline__ int ld_acq(const int* p) {
    int v;
    asm volatile("ld.acquire.cta.b32 %0, [%1];" : "=r"(v) : "l"(p) : "memory");
    return v;
}
__device__ __forceinline__ void st_rel(int* p, int v) {
    asm volatile("st.release.cta.b32 [%0], %1;" :: "l"(p), "r"(v) : "memory");
}

// ================= K1: priors =================
// Replays reference op order: mul+add+relu, fma-accumulate ascending j,
// +b2, max, shift, sequential exp-sum, log. Stores NEGATED log_softmax,
// permuted into E/O halves.
__global__ void k_priors(const float* __restrict__ rx,
                         const float* __restrict__ W1,
                         const float* __restrict__ b1,
                         const float* __restrict__ W2,
                         const float* __restrict__ b2,
                         int T) {
    __shared__ float sW1[HIDDEN], sb1[HIDDEN], sW2[HIDDEN * NS], sb2[NS];
    for (int i = threadIdx.x; i < HIDDEN; i += blockDim.x) { sW1[i] = W1[i]; sb1[i] = b1[i]; }
    for (int i = threadIdx.x; i < HIDDEN * NS; i += blockDim.x) sW2[i] = W2[i];
    if (threadIdx.x < NS) sb2[threadIdx.x] = b2[threadIdx.x];
    __syncthreads();

    int t = blockIdx.x * blockDim.x + threadIdx.x;
    if (t >= T) return;

    float x = rx[t];
    float acc[NS];
#pragma unroll
    for (int i = 0; i < NS; i++) acc[i] = 0.0f;

    for (int j = 0; j < HIDDEN; j++) {
        float h = __fadd_rn(__fmul_rn(x, sW1[j]), sb1[j]);
        h = fmaxf(h, 0.0f);
#pragma unroll
        for (int i = 0; i < NS; i++) acc[i] = fmaf(h, sW2[j * NS + i], acc[i]);
    }
#pragma unroll
    for (int i = 0; i < NS; i++) acc[i] = __fadd_rn(acc[i], sb2[i]);

    float m = acc[0];
#pragma unroll
    for (int i = 1; i < NS; i++) m = fmaxf(m, acc[i]);

    float sh[NS];
    float s = 0.0f;
#pragma unroll
    for (int i = 0; i < NS; i++) {
        sh[i] = __fadd_rn(acc[i], -m);
        s = __fadd_rn(s, expf(sh[i]));
    }
    float L = logf(s);

    float* dst = g_np + (size_t)t * NS;
#pragma unroll
    for (int i = 0; i < 8; i++) {
        dst[i]     = __fadd_rn(L, -sh[2 * i]);       // E half: np_{2i}
        dst[8 + i] = __fadd_rn(L, -sh[2 * i + 1]);   // O half: np_{2i+1}
    }
}

// ================= K2: exact sequential scan =================
// Warp 0: packed E/O datapath. State held as 4 b64 pairs:
//   A=(p0,p2)  B=(p4,p6)  C=(p1,p3)  D=(p5,p7)
// Per step: E = (A,B,A,B) + npE, O = (C,D,C,D) + npO  (8x FFMA2, mult=(1,1),
// bit-equal to FADD — proven R2->R3 rel_err invariant), then elementwise
// p_new = min(E,O) as 8x scalar min.f32 whose outputs repack (via register
// renaming, no data movement) into A',B',C',D'.
// Warps 1-3: stage priors global->smem ring (own SMSPs; spins steal no scan slots).
__global__ void __launch_bounds__(128, 1) k_scan() {
    __shared__ __align__(16) float ring[RB * BS * 16];   // 32 KB
    __shared__ int flag[RB];
    __shared__ int consumed;

    const int tid  = threadIdx.x;
    const int wid  = tid >> 5;
    const int lane = tid & 31;

    if (tid < RB) flag[tid] = 0;
    if (tid == 0) consumed = 0;
    __syncthreads();

    if (wid == 0) {
        unsigned long long A = 0ull, B = 0ull, C = 0ull, D = 0ull;   // zeros
        const unsigned long long ONE = 0x3F8000003F800000ULL;        // (1.0f,1.0f)
        for (int b = 0; b < NBLK; b++) {
            if (lane == 0) {
                float* cp = g_ckpt + (size_t)b * 8;
                asm volatile("st.global.v2.u64 [%0], {%1,%2};" :: "l"(cp),     "l"(A), "l"(B) : "memory");
                asm volatile("st.global.v2.u64 [%0], {%1,%2};" :: "l"(cp + 4), "l"(C), "l"(D) : "memory");
            }
            while (ld_acq(&flag[b & (RB - 1)]) != b + 1) { }
            unsigned sbase = (unsigned)__cvta_generic_to_shared(&ring[(b & (RB - 1)) * (BS * 16)]);
#pragma unroll 1
            for (int kk = 0; kk < BS; kk += 16) {
#pragma unroll
                for (int k2 = 0; k2 < 16; k2++) {
                    unsigned addr = sbase + (kk + k2) * 64;
                    asm("{\n\t"
                        ".reg .b64 ne0,ne1,ne2,ne3,no0,no1,no2,no3;\n\t"
                        ".reg .b64 w0,w1,w2,w3,x0,x1,x2,x3;\n\t"
                        ".reg .f32 we0,we1,we2,we3,we4,we5,we6,we7;\n\t"
                        ".reg .f32 xe0,xe1,xe2,xe3,xe4,xe5,xe6,xe7;\n\t"
                        ".reg .f32 t0,t1,t2,t3,t4,t5,t6,t7;\n\t"
                        "ld.shared.v2.u64 {ne0,ne1}, [%4];\n\t"
                        "ld.shared.v2.u64 {ne2,ne3}, [%4+16];\n\t"
                        "ld.shared.v2.u64 {no0,no1}, [%4+32];\n\t"
                        "ld.shared.v2.u64 {no2,no3}, [%4+48];\n\t"
                        "fma.rn.f32x2 w0, %0, %5, ne0;\n\t"
                        "fma.rn.f32x2 w1, %1, %5, ne1;\n\t"
                        "fma.rn.f32x2 w2, %0, %5, ne2;\n\t"
                        "fma.rn.f32x2 w3, %1, %5, ne3;\n\t"
                        "fma.rn.f32x2 x0, %2, %5, no0;\n\t"
                        "fma.rn.f32x2 x1, %3, %5, no1;\n\t"
                        "fma.rn.f32x2 x2, %2, %5, no2;\n\t"
                        "fma.rn.f32x2 x3, %3, %5, no3;\n\t"
                        "mov.b64 {we0,we1}, w0;\n\t"
                        "mov.b64 {we2,we3}, w1;\n\t"
                        "mov.b64 {we4,we5}, w2;\n\t"
                        "mov.b64 {we6,we7}, w3;\n\t"
                        "mov.b64 {xe0,xe1}, x0;\n\t"
                        "mov.b64 {xe2,xe3}, x1;\n\t"
                        "mov.b64 {xe4,xe5}, x2;\n\t"
                        "mov.b64 {xe6,xe7}, x3;\n\t"
                        "min.f32 t0, we0, xe0;\n\t"   // pn0
                        "min.f32 t1, we1, xe1;\n\t"   // pn1
                        "min.f32 t2, we2, xe2;\n\t"   // pn2
                        "min.f32 t3, we3, xe3;\n\t"   // pn3
                        "min.f32 t4, we4, xe4;\n\t"   // pn4
                        "min.f32 t5, we5, xe5;\n\t"   // pn5
                        "min.f32 t6, we6, xe6;\n\t"   // pn6
                        "min.f32 t7, we7, xe7;\n\t"   // pn7
                        "mov.b64 %0, {t0,t2};\n\t"    // A' = (pn0,pn2)
                        "mov.b64 %1, {t4,t6};\n\t"    // B' = (pn4,pn6)
                        "mov.b64 %2, {t1,t3};\n\t"    // C' = (pn1,pn3)
                        "mov.b64 %3, {t5,t7};\n\t"    // D' = (pn5,pn7)
                        "}"
                        : "+l"(A), "+l"(B), "+l"(C), "+l"(D)
                        : "r"(addr), "l"(ONE)
                        : "memory");
                }
            }
            if (lane == 0) st_rel(&consumed, b + 1);
        }
    } else {
        // copier warps: wid 1..3 handle blocks b with b % 3 == wid-1
        for (int b = wid - 1; b < NBLK; b += 3) {
            while (b >= RB && ld_acq(&consumed) < b - RB + 1) __nanosleep(100);
            const float4* src = (const float4*)(g_np + (size_t)b * (BS * 16));
            float4* dst = (float4*)&ring[(b & (RB - 1)) * (BS * 16)];
#pragma unroll
            for (int r = 0; r < 8; r++) dst[r * 32 + lane] = src[r * 32 + lane];
            __syncwarp();
            if (lane == 0) st_rel(&flag[b & (RB - 1)], b + 1);
        }
    }
}

// ================= K3: parallel det/conf emission =================
// Each thread replays one 64-step chunk bit-exactly from its checkpoint.
// Checkpoint layout: [p0,p2,p4,p6, p1,p3,p5,p7]; np layout: E half then O half.
__global__ void k_emit(float* __restrict__ out_det, float* __restrict__ out_conf) {
    int c = blockIdx.x * blockDim.x + threadIdx.x;
    if (c >= NBLK) return;

    float p[8];
    float4 a = *(const float4*)(g_ckpt + (size_t)c * 8);
    float4 b = *(const float4*)(g_ckpt + (size_t)c * 8 + 4);
    p[0] = a.x; p[2] = a.y; p[4] = a.z; p[6] = a.w;
    p[1] = b.x; p[3] = b.y; p[5] = b.z; p[7] = b.w;

    const float* np = g_np + (size_t)c * (BS * 16);
    const int tbase = c * BS;

    for (int k = 0; k < BS; k++) {
        // det: first-index argmin over p[0..7], parity
        float best = p[0];
        int idx = 0;
#pragma unroll
        for (int j = 1; j < 8; j++) {
            if (p[j] < best) { best = p[j]; idx = j; }
        }
        // conf: S = sum_{j=0..15} exp(pmin - p_j) with duplicated halves,
        // sequential ascending; 2*conf = 2*(1/S)
        float e[8];
#pragma unroll
        for (int j = 0; j < 8; j++) e[j] = expf(__fadd_rn(best, -p[j]));
        float S = e[0];
#pragma unroll
        for (int j = 1; j < 8; j++) S = __fadd_rn(S, e[j]);
#pragma unroll
        for (int j = 0; j < 8; j++) S = __fadd_rn(S, e[j]);
        float conf = __fdiv_rn(1.0f, S);

        out_det[tbase + k]  = (float)(idx & 1);
        out_conf[tbase + k] = __fmul_rn(2.0f, conf);

        // update, identical arithmetic to K2 packed ops:
        // p_new[i] = min(p[(2i)&7] + E_i, p[((2i)&7)+1] + O_i)
        const float* q = np + k * 16;
        float4 q0 = *(const float4*)(q);       // E0..E3
        float4 q1 = *(const float4*)(q + 4);   // E4..E7
        float4 q2 = *(const float4*)(q + 8);   // O0..O3
        float4 q3 = *(const float4*)(q + 12);  // O4..O7
        float E[8] = { q0.x, q0.y, q0.z, q0.w,  q1.x, q1.y, q1.z, q1.w };
        float O[8] = { q2.x, q2.y, q2.z, q2.w,  q3.x, q3.y, q3.z, q3.w };
        float newp[8];
#pragma unroll
        for (int i = 0; i < 8; i++) {
            int a2 = (2 * i) & 7;
            newp[i] = fminf(__fadd_rn(p[a2],     E[i]),
                            __fadd_rn(p[a2 + 1], O[i]));
        }
#pragma unroll
        for (int i = 0; i < 8; i++) p[i] = newp[i];
    }
}

// ================= launch =================
extern "C" void kernel_launch(void* const* d_in, const int* in_sizes, int n_in,
                              void* d_out, int out_size) {
    const float* rx = (const float*)d_in[0];
    const float* W1 = (const float*)d_in[1];
    const float* b1 = (const float*)d_in[2];
    const float* W2 = (const float*)d_in[3];
    const float* b2 = (const float*)d_in[4];
    float* out = (float*)d_out;

    int T = in_sizes[0];
    if (T > T_LEN) T = T_LEN;

    k_priors<<<(T + 255) / 256, 256>>>(rx, W1, b1, W2, b2, T);
    k_scan<<<1, 128>>>();
    k_emit<<<(NBLK + 127) / 128, 128>>>(out, out + T);
}